// round 9
// baseline (speedup 1.0000x reference)
#include <cuda_runtime.h>
#include <math.h>
#include <float.h>

#define H 1024
#define V 50257
#define S 4096
#define ABLK 256                        // kernel A blocks
#define LBLK2 592                       // kernel B blocks = 148 SMs x 4 CTAs
#define NWARP (LBLK2 * 8)               // 4736 logits warps
#define CHUNK2 ((V + LBLK2 - 1) / LBLK2)  // 85

// ---------------- scratch (device globals; no allocation allowed) ----------
__device__ float g_hnew[H];
__device__ float g_context[H];
__device__ float g_bmax[ABLK];
__device__ float g_bsum[ABLK];
__device__ float g_ctx_part[ABLK * H];
__device__ float g_logits[V];
__device__ float g_lse_m[LBLK2];
__device__ float g_lse_s[LBLK2];
__device__ unsigned int g_cnt;          // always returns to 0 after a barrier
__device__ unsigned int g_gen;          // monotonic; wrap-safe

// ---------------- helpers --------------------------------------------------
__device__ __forceinline__ float dot4(float4 a, float4 b) {
    return a.x * b.x + a.y * b.y + a.z * b.z + a.w * b.w;
}
__device__ __forceinline__ float warp_sum(float v) {
    #pragma unroll
    for (int o = 16; o > 0; o >>= 1) v += __shfl_xor_sync(0xffffffffu, v, o);
    return v;
}
__device__ __forceinline__ float warp_max(float v) {
    #pragma unroll
    for (int o = 16; o > 0; o >>= 1) v = fmaxf(v, __shfl_xor_sync(0xffffffffu, v, o));
    return v;
}
__device__ __forceinline__ void lse_merge(float& m, float& s, float om, float os) {
    float nm = fmaxf(m, om);              // operands finite (-FLT_MAX pad)
    s = s * expf(m - nm) + os * expf(om - nm);
    m = nm;
}
// generation-based grid barrier; stateless after release (cnt back to 0).
__device__ __forceinline__ void gbar(unsigned int target) {
    __syncthreads();
    if (threadIdx.x == 0) {
        __threadfence();
        unsigned int gen = atomicAdd(&g_gen, 0u);   // read BEFORE arriving
        unsigned int old = atomicAdd(&g_cnt, 1u);
        if (old == target - 1) {
            atomicExch(&g_cnt, 0u);
            __threadfence();
            atomicAdd(&g_gen, 1u);                   // release
        } else {
            while (atomicAdd(&g_gen, 0u) == gen) __nanosleep(40);
        }
    }
    __syncthreads();
    __threadfence();
}

// ============ Kernel A: GRU + attention. 256 blocks x 256 threads ==========
__global__ void __launch_bounds__(256, 2)
gru_attn_kernel(const int* __restrict__ word,
                const float* __restrict__ last_ctx,
                const float* __restrict__ last_h,
                const float* __restrict__ enc,
                const float* __restrict__ emb,
                const float* __restrict__ w_ih,
                const float* __restrict__ w_hh,
                const float* __restrict__ b_ih,
                const float* __restrict__ b_hh,
                float* __restrict__ d_out) {
    const int b = blockIdx.x;
    const int tid = threadIdx.x;
    const int warp = tid >> 5, lane = tid & 31;

    __shared__ float sc[16], ev[16], av[16];
    __shared__ float r8[8];
    __shared__ float4 r84[8];
    __shared__ float bc, bc2;

    // -------- Phase A: GRU, rows j = b + 256k, k<4 --------
    {
        const float4* e4 = (const float4*)(emb + (size_t)word[0] * H);
        const float4* c4 = (const float4*)last_ctx;
        const float4* h4 = (const float4*)last_h;
        __shared__ float red[6][8];
        #pragma unroll 1
        for (int j = b; j < H; j += ABLK) {
            const float4* wr = (const float4*)(w_ih + (size_t)(j)       * 2 * H);
            const float4* wz = (const float4*)(w_ih + (size_t)(j + H)   * 2 * H);
            const float4* wn = (const float4*)(w_ih + (size_t)(j + 2*H) * 2 * H);
            const float4* ur = (const float4*)(w_hh + (size_t)(j)       * H);
            const float4* uz = (const float4*)(w_hh + (size_t)(j + H)   * H);
            const float4* un = (const float4*)(w_hh + (size_t)(j + 2*H) * H);

            float ar = 0.f, az = 0.f, an = 0.f, br2 = 0.f, bz = 0.f, bn = 0.f;
            #pragma unroll
            for (int k = 0; k < 2; k++) {
                int c = tid + 256 * k;
                float4 x = (c < 256) ? e4[c] : c4[c - 256];
                ar += dot4(wr[c], x);
                az += dot4(wz[c], x);
                an += dot4(wn[c], x);
            }
            {
                float4 hh = h4[tid];
                br2 += dot4(ur[tid], hh);
                bz  += dot4(uz[tid], hh);
                bn  += dot4(un[tid], hh);
            }
            ar = warp_sum(ar); az = warp_sum(az); an = warp_sum(an);
            br2 = warp_sum(br2); bz = warp_sum(bz); bn = warp_sum(bn);
            if (lane == 0) {
                red[0][warp] = ar;  red[1][warp] = az;  red[2][warp] = an;
                red[3][warp] = br2; red[4][warp] = bz;  red[5][warp] = bn;
            }
            __syncthreads();
            if (tid == 0) {
                float s[6];
                #pragma unroll
                for (int k = 0; k < 6; k++) {
                    float acc = red[k][0];
                    #pragma unroll
                    for (int q = 1; q < 8; q++) acc += red[k][q];
                    s[k] = acc;
                }
                float ir = s[0] + b_ih[j];
                float iz = s[1] + b_ih[j + H];
                float in_ = s[2] + b_ih[j + 2 * H];
                float hr = s[3] + b_hh[j];
                float hz = s[4] + b_hh[j + H];
                float hn = s[5] + b_hh[j + 2 * H];
                float r = 1.f / (1.f + expf(-(ir + hr)));
                float z = 1.f / (1.f + expf(-(iz + hz)));
                float n = tanhf(in_ + r * hn);
                float hv = last_h[j];
                float hnew = (1.f - z) * n + z * hv;
                g_hnew[j] = hnew;
                d_out[V + H + j] = hnew;           // h_new slot
            }
            __syncthreads();
        }
    }
    gbar(ABLK);

    // -------- Phase B: scores for rows [16b, 16b+16) --------
    const float4* enc4 = (const float4*)enc;
    #pragma unroll
    for (int rr = 0; rr < 2; rr++) {
        int local = warp * 2 + rr;
        const float4* e4 = enc4 + (size_t)(b * 16 + local) * 256;
        float a0 = 0.f, a1 = 0.f;
        #pragma unroll
        for (int k = 0; k < 8; k += 2) {
            a0 += dot4(e4[lane + 32 * k],       __ldcg(&((const float4*)g_hnew)[lane + 32 * k]));
            a1 += dot4(e4[lane + 32 * (k + 1)], __ldcg(&((const float4*)g_hnew)[lane + 32 * (k + 1)]));
        }
        float acc = warp_sum(a0 + a1);
        if (lane == 0) sc[local] = acc;
    }
    __syncthreads();
    if (tid < 32) {
        float v = (lane < 16) ? sc[lane] : -FLT_MAX;
        v = warp_max(v);
        if (lane == 0) g_bmax[b] = v;
    }
    gbar(ABLK);

    // -------- Phase C: global max, exp, block partial sum --------
    {
        float v = __ldcg(&g_bmax[tid]);
        v = warp_max(v);
        if (lane == 0) r8[warp] = v;
        __syncthreads();
        if (tid == 0) {
            float m = r8[0];
            #pragma unroll
            for (int k = 1; k < 8; k++) m = fmaxf(m, r8[k]);
            bc = m;
        }
        __syncthreads();
        float M = bc;
        if (tid < 16) ev[tid] = expf(sc[tid] - M);
        __syncthreads();
        if (tid < 32) {
            float e = (lane < 16) ? ev[lane] : 0.f;
            e = warp_sum(e);
            if (lane == 0) g_bsum[b] = e;
        }
    }
    gbar(ABLK);

    // -------- Phase D: normalize, attn out, ctx partial --------
    {
        float v = __ldcg(&g_bsum[tid]);
        v = warp_sum(v);
        if (lane == 0) r8[warp] = v;
        __syncthreads();
        if (tid == 0) {
            float z = r8[0];
            #pragma unroll
            for (int k = 1; k < 8; k++) z += r8[k];
            bc2 = 1.f / z;
        }
        __syncthreads();
        float invZ = bc2;
        if (tid < 16) {
            float a = ev[tid] * invZ;
            av[tid] = a;
            d_out[V + 2 * H + b * 16 + tid] = a;   // attn slot
        }
        __syncthreads();
        const float4* e4 = enc4 + (size_t)(b * 16) * 256;
        float4 acc = make_float4(0.f, 0.f, 0.f, 0.f);
        #pragma unroll
        for (int i = 0; i < 16; i++) {
            float a = av[i];
            float4 e = e4[(size_t)i * 256 + tid];  // L1-hot from phase B
            acc.x += a * e.x; acc.y += a * e.y; acc.z += a * e.z; acc.w += a * e.w;
        }
        ((float4*)g_ctx_part)[b * 256 + tid] = acc;
    }
    gbar(ABLK);

    // -------- Phase E: ctx reduce -> context[4b .. 4b+3] --------
    {
        float4 val = __ldcg(&((const float4*)g_ctx_part)[(size_t)tid * 256 + b]);
        val.x = warp_sum(val.x); val.y = warp_sum(val.y);
        val.z = warp_sum(val.z); val.w = warp_sum(val.w);
        if (lane == 0) r84[warp] = val;
        __syncthreads();
        if (tid == 0) {
            float4 s = r84[0];
            #pragma unroll
            for (int k = 1; k < 8; k++) {
                s.x += r84[k].x; s.y += r84[k].y; s.z += r84[k].z; s.w += r84[k].w;
            }
            ((float4*)g_context)[b] = s;
            d_out[V + 4 * b + 0] = s.x;            // context slot
            d_out[V + 4 * b + 1] = s.y;
            d_out[V + 4 * b + 2] = s.z;
            d_out[V + 4 * b + 3] = s.w;
        }
    }
}

// ============ Kernel B: logits + LSE + write. 592 blocks x 256 =============
// launch_bounds(256,4): <=64 regs -> exactly 4 CTAs/SM co-resident (barrier-safe),
// 32 warps/SM for DRAM saturation.
__global__ void __launch_bounds__(256, 4)
logits_lse_kernel(const float* __restrict__ out_w,
                  const float* __restrict__ out_b,
                  float* __restrict__ d_out) {
    const int b = blockIdx.x;
    const int tid = threadIdx.x;
    const int warp = tid >> 5, lane = tid & 31;

    __shared__ float4 xs[512];          // x = [h_new | context]
    __shared__ float shm[8], shs[8];

    xs[tid]       = ((const float4*)g_hnew)[tid];
    xs[tid + 256] = ((const float4*)g_context)[tid];
    __syncthreads();

    // persistent warp-per-row logits + online lse
    const float4* w_base = (const float4*)out_w;
    float wm = -FLT_MAX, ws = 0.f;
    const int gw = b * 8 + warp;
    for (int row = gw; row < V; row += NWARP) {
        const float4* w4 = w_base + (size_t)row * 512;
        float a0 = 0.f, a1 = 0.f, a2 = 0.f, a3 = 0.f;
        #pragma unroll
        for (int k = 0; k < 16; k += 4) {
            a0 += dot4(w4[lane + 32 * (k + 0)], xs[lane + 32 * (k + 0)]);
            a1 += dot4(w4[lane + 32 * (k + 1)], xs[lane + 32 * (k + 1)]);
            a2 += dot4(w4[lane + 32 * (k + 2)], xs[lane + 32 * (k + 2)]);
            a3 += dot4(w4[lane + 32 * (k + 3)], xs[lane + 32 * (k + 3)]);
        }
        float logit = warp_sum((a0 + a1) + (a2 + a3)) + out_b[row];
        if (lane == 0) {
            g_logits[row] = logit;
            lse_merge(wm, ws, logit, 1.f);
        }
    }
    if (lane == 0) { shm[warp] = wm; shs[warp] = ws; }
    __syncthreads();
    if (tid == 0) {
        float mm = shm[0], sacc = shs[0];
        #pragma unroll
        for (int k = 1; k < 8; k++) lse_merge(mm, sacc, shm[k], shs[k]);
        g_lse_m[b] = mm;
        g_lse_s[b] = sacc;
    }
    gbar(LBLK2);

    // merge 592 partials -> logz, then write this block's output chunk
    float m = -FLT_MAX, s = 0.f;
    for (int k = tid; k < LBLK2; k += 256)
        lse_merge(m, s, __ldcg(&g_lse_m[k]), __ldcg(&g_lse_s[k]));
    #pragma unroll
    for (int o = 16; o > 0; o >>= 1) {
        float om = __shfl_xor_sync(0xffffffffu, m, o);
        float os = __shfl_xor_sync(0xffffffffu, s, o);
        lse_merge(m, s, om, os);
    }
    __syncthreads();                  // shm/shs reuse guard
    if (lane == 0) { shm[warp] = m; shs[warp] = s; }
    __syncthreads();
    __shared__ float sz;
    if (tid == 0) {
        float mm = shm[0], sacc = shs[0];
        #pragma unroll
        for (int k = 1; k < 8; k++) lse_merge(mm, sacc, shm[k], shs[k]);
        sz = mm + logf(sacc);
    }
    __syncthreads();
    float logz = sz;
    int v = b * CHUNK2 + tid;
    if (tid < CHUNK2 && v < V)
        d_out[v] = __ldcg(&g_logits[v]) - logz;
}

// ---------------- launch ---------------------------------------------------
extern "C" void kernel_launch(void* const* d_in, const int* in_sizes, int n_in,
                              void* d_out, int out_size) {
    const int*   word     = (const int*)  d_in[0];
    const float* last_ctx = (const float*)d_in[1];
    const float* last_h   = (const float*)d_in[2];
    const float* enc      = (const float*)d_in[3];
    const float* emb      = (const float*)d_in[4];
    const float* w_ih     = (const float*)d_in[5];
    const float* w_hh     = (const float*)d_in[6];
    const float* b_ih     = (const float*)d_in[7];
    const float* b_hh     = (const float*)d_in[8];
    const float* out_w    = (const float*)d_in[9];
    const float* out_b    = (const float*)d_in[10];
    float* out = (float*)d_out;

    gru_attn_kernel<<<ABLK, 256>>>(word, last_ctx, last_h, enc, emb,
                                   w_ih, w_hh, b_ih, b_hh, out);
    logits_lse_kernel<<<LBLK2, 256>>>(out_w, out_b, out);
}

// round 10
// speedup vs baseline: 1.2118x; 1.2118x over previous
#include <cuda_runtime.h>
#include <math.h>
#include <float.h>

#define H 1024
#define V 50257
#define S 4096
#define ABLK 256      // kernel A blocks (persistent, co-resident)
#define LBLK 197      // kernel C blocks

// ---------------- scratch (device globals; no allocation allowed) ----------
__device__ float g_hnew[H];
__device__ float g_context[H];
__device__ float g_bmax[ABLK];
__device__ float g_bsum[ABLK];
__device__ float g_ctx_part[ABLK * H];
__device__ float g_logits[V];
__device__ float g_lse_m[LBLK];
__device__ float g_lse_s[LBLK];
__device__ unsigned int g_cnt;          // returns to 0 after every barrier
__device__ unsigned int g_gen;          // monotonic; wrap-safe

// ---------------- helpers --------------------------------------------------
__device__ __forceinline__ float dot4(float4 a, float4 b) {
    return a.x * b.x + a.y * b.y + a.z * b.z + a.w * b.w;
}
__device__ __forceinline__ float warp_sum(float v) {
    #pragma unroll
    for (int o = 16; o > 0; o >>= 1) v += __shfl_xor_sync(0xffffffffu, v, o);
    return v;
}
__device__ __forceinline__ float warp_max(float v) {
    #pragma unroll
    for (int o = 16; o > 0; o >>= 1) v = fmaxf(v, __shfl_xor_sync(0xffffffffu, v, o));
    return v;
}
__device__ __forceinline__ void lse_merge(float& m, float& s, float om, float os) {
    float nm = fmaxf(m, om);              // operands finite (-FLT_MAX pad)
    s = s * expf(m - nm) + os * expf(om - nm);
    m = nm;
}
// generation-based grid barrier; stateless after release (cnt back to 0).
__device__ __forceinline__ void gbar(unsigned int target) {
    __syncthreads();
    if (threadIdx.x == 0) {
        __threadfence();
        unsigned int gen = atomicAdd(&g_gen, 0u);   // read BEFORE arriving
        unsigned int old = atomicAdd(&g_cnt, 1u);
        if (old == target - 1) {
            atomicExch(&g_cnt, 0u);
            __threadfence();
            atomicAdd(&g_gen, 1u);                   // release
        } else {
            while (atomicAdd(&g_gen, 0u) == gen) __nanosleep(40);
        }
    }
    __syncthreads();
    __threadfence();
}

// ============ Kernel A: GRU + attention. 256 blocks x 256 threads ==========
__global__ void __launch_bounds__(256, 2)
gru_attn_kernel(const int* __restrict__ word,
                const float* __restrict__ last_ctx,
                const float* __restrict__ last_h,
                const float* __restrict__ enc,
                const float* __restrict__ emb,
                const float* __restrict__ w_ih,
                const float* __restrict__ w_hh,
                const float* __restrict__ b_ih,
                const float* __restrict__ b_hh,
                float* __restrict__ d_out) {
    const int b = blockIdx.x;
    const int tid = threadIdx.x;
    const int warp = tid >> 5, lane = tid & 31;

    __shared__ float sc[16], ev[16], av[16];
    __shared__ float r8[8];
    __shared__ float4 r84[8];
    __shared__ float bc, bc2;

    // -------- Phase A: GRU, rows j = b + 256k, k<4 --------
    {
        const float4* e4 = (const float4*)(emb + (size_t)word[0] * H);
        const float4* c4 = (const float4*)last_ctx;
        const float4* h4 = (const float4*)last_h;
        __shared__ float red[6][8];
        #pragma unroll 1
        for (int j = b; j < H; j += ABLK) {
            const float4* wr = (const float4*)(w_ih + (size_t)(j)       * 2 * H);
            const float4* wz = (const float4*)(w_ih + (size_t)(j + H)   * 2 * H);
            const float4* wn = (const float4*)(w_ih + (size_t)(j + 2*H) * 2 * H);
            const float4* ur = (const float4*)(w_hh + (size_t)(j)       * H);
            const float4* uz = (const float4*)(w_hh + (size_t)(j + H)   * H);
            const float4* un = (const float4*)(w_hh + (size_t)(j + 2*H) * H);

            float ar = 0.f, az = 0.f, an = 0.f, br2 = 0.f, bz = 0.f, bn = 0.f;
            #pragma unroll
            for (int k = 0; k < 2; k++) {
                int c = tid + 256 * k;
                float4 x = (c < 256) ? e4[c] : c4[c - 256];
                ar += dot4(wr[c], x);
                az += dot4(wz[c], x);
                an += dot4(wn[c], x);
            }
            {
                float4 hh = h4[tid];
                br2 += dot4(ur[tid], hh);
                bz  += dot4(uz[tid], hh);
                bn  += dot4(un[tid], hh);
            }
            ar = warp_sum(ar); az = warp_sum(az); an = warp_sum(an);
            br2 = warp_sum(br2); bz = warp_sum(bz); bn = warp_sum(bn);
            if (lane == 0) {
                red[0][warp] = ar;  red[1][warp] = az;  red[2][warp] = an;
                red[3][warp] = br2; red[4][warp] = bz;  red[5][warp] = bn;
            }
            __syncthreads();
            if (tid == 0) {
                float s[6];
                #pragma unroll
                for (int k = 0; k < 6; k++) {
                    float acc = red[k][0];
                    #pragma unroll
                    for (int q = 1; q < 8; q++) acc += red[k][q];
                    s[k] = acc;
                }
                float ir = s[0] + b_ih[j];
                float iz = s[1] + b_ih[j + H];
                float in_ = s[2] + b_ih[j + 2 * H];
                float hr = s[3] + b_hh[j];
                float hz = s[4] + b_hh[j + H];
                float hn = s[5] + b_hh[j + 2 * H];
                float r = 1.f / (1.f + expf(-(ir + hr)));
                float z = 1.f / (1.f + expf(-(iz + hz)));
                float n = tanhf(in_ + r * hn);
                float hv = last_h[j];
                float hnew = (1.f - z) * n + z * hv;
                g_hnew[j] = hnew;
                d_out[V + H + j] = hnew;           // h_new slot
            }
            __syncthreads();
        }
    }
    gbar(ABLK);

    // -------- Phase B: scores for rows [16b, 16b+16) --------
    const float4* enc4 = (const float4*)enc;
    #pragma unroll
    for (int rr = 0; rr < 2; rr++) {
        int local = warp * 2 + rr;
        const float4* e4 = enc4 + (size_t)(b * 16 + local) * 256;
        float a0 = 0.f, a1 = 0.f;
        #pragma unroll
        for (int k = 0; k < 8; k += 2) {
            a0 += dot4(e4[lane + 32 * k],       __ldcg(&((const float4*)g_hnew)[lane + 32 * k]));
            a1 += dot4(e4[lane + 32 * (k + 1)], __ldcg(&((const float4*)g_hnew)[lane + 32 * (k + 1)]));
        }
        float acc = warp_sum(a0 + a1);
        if (lane == 0) sc[local] = acc;
    }
    __syncthreads();
    if (tid < 32) {
        float v = (lane < 16) ? sc[lane] : -FLT_MAX;
        v = warp_max(v);
        if (lane == 0) g_bmax[b] = v;
    }
    gbar(ABLK);

    // -------- Phase C: global max, exp, block partial sum --------
    {
        float v = __ldcg(&g_bmax[tid]);
        v = warp_max(v);
        if (lane == 0) r8[warp] = v;
        __syncthreads();
        if (tid == 0) {
            float m = r8[0];
            #pragma unroll
            for (int k = 1; k < 8; k++) m = fmaxf(m, r8[k]);
            bc = m;
        }
        __syncthreads();
        float M = bc;
        if (tid < 16) ev[tid] = expf(sc[tid] - M);
        __syncthreads();
        if (tid < 32) {
            float e = (lane < 16) ? ev[lane] : 0.f;
            e = warp_sum(e);
            if (lane == 0) g_bsum[b] = e;
        }
    }
    gbar(ABLK);

    // -------- Phase D: normalize, attn out, ctx partial --------
    {
        float v = __ldcg(&g_bsum[tid]);
        v = warp_sum(v);
        if (lane == 0) r8[warp] = v;
        __syncthreads();
        if (tid == 0) {
            float z = r8[0];
            #pragma unroll
            for (int k = 1; k < 8; k++) z += r8[k];
            bc2 = 1.f / z;
        }
        __syncthreads();
        float invZ = bc2;
        if (tid < 16) {
            float a = ev[tid] * invZ;
            av[tid] = a;
            d_out[V + 2 * H + b * 16 + tid] = a;   // attn slot
        }
        __syncthreads();
        const float4* e4 = enc4 + (size_t)(b * 16) * 256;
        float4 acc = make_float4(0.f, 0.f, 0.f, 0.f);
        #pragma unroll
        for (int i = 0; i < 16; i++) {
            float a = av[i];
            float4 e = e4[(size_t)i * 256 + tid];  // L1-hot from phase B
            acc.x += a * e.x; acc.y += a * e.y; acc.z += a * e.z; acc.w += a * e.w;
        }
        ((float4*)g_ctx_part)[b * 256 + tid] = acc;
    }
    gbar(ABLK);

    // -------- Phase E: ctx reduce -> context[4b .. 4b+3] --------
    {
        float4 val = __ldcg(&((const float4*)g_ctx_part)[(size_t)tid * 256 + b]);
        val.x = warp_sum(val.x); val.y = warp_sum(val.y);
        val.z = warp_sum(val.z); val.w = warp_sum(val.w);
        if (lane == 0) r84[warp] = val;
        __syncthreads();
        if (tid == 0) {
            float4 s = r84[0];
            #pragma unroll
            for (int k = 1; k < 8; k++) {
                s.x += r84[k].x; s.y += r84[k].y; s.z += r84[k].z; s.w += r84[k].w;
            }
            ((float4*)g_context)[b] = s;
            d_out[V + 4 * b + 0] = s.x;            // context slot
            d_out[V + 4 * b + 1] = s.y;
            d_out[V + 4 * b + 2] = s.z;
            d_out[V + 4 * b + 3] = s.w;
        }
    }
}

// ============ Kernel B: logits. V blocks x 128 (proven 6.9 TB/s) ===========
__global__ void __launch_bounds__(128) logits_kernel(const float* __restrict__ out_w,
                                                     const float* __restrict__ out_b) {
    const int v = blockIdx.x;
    const int tid = threadIdx.x;
    const float4* w4 = (const float4*)(out_w + (size_t)v * 2 * H);
    const float4* h4 = (const float4*)g_hnew;
    const float4* c4 = (const float4*)g_context;
    float acc = 0.f;
    #pragma unroll
    for (int k = 0; k < 4; k++) {
        int c = tid + 128 * k;
        float4 x = (k < 2) ? h4[c] : c4[c - 256];
        acc += dot4(w4[c], x);
    }
    acc = warp_sum(acc);
    __shared__ float red[4];
    if ((tid & 31) == 0) red[tid >> 5] = acc;
    __syncthreads();
    if (tid == 0) g_logits[v] = red[0] + red[1] + red[2] + red[3] + out_b[v];
}

// ============ Kernel C: fused logsumexp + write. 197 blocks x 256 ==========
__global__ void __launch_bounds__(256) lse_write_kernel(float* __restrict__ d_out) {
    const int b = blockIdx.x;
    const int tid = threadIdx.x;
    const int warp = tid >> 5, lane = tid & 31;
    const int v = b * 256 + tid;

    float m = (v < V) ? g_logits[v] : -FLT_MAX;
    float s = (v < V) ? 1.f : 0.f;
    #pragma unroll
    for (int o = 16; o > 0; o >>= 1) {
        float om = __shfl_xor_sync(0xffffffffu, m, o);
        float os = __shfl_xor_sync(0xffffffffu, s, o);
        lse_merge(m, s, om, os);
    }
    __shared__ float shm[8], shs[8];
    if (lane == 0) { shm[warp] = m; shs[warp] = s; }
    __syncthreads();
    if (tid == 0) {
        float mm = shm[0], sacc = shs[0];
        #pragma unroll
        for (int k = 1; k < 8; k++) lse_merge(mm, sacc, shm[k], shs[k]);
        g_lse_m[b] = mm;
        g_lse_s[b] = sacc;
    }
    gbar(LBLK);

    float m2 = (tid < LBLK) ? __ldcg(&g_lse_m[tid]) : -FLT_MAX;
    float s2 = (tid < LBLK) ? __ldcg(&g_lse_s[tid]) : 0.f;
    #pragma unroll
    for (int o = 16; o > 0; o >>= 1) {
        float om = __shfl_xor_sync(0xffffffffu, m2, o);
        float os = __shfl_xor_sync(0xffffffffu, s2, o);
        lse_merge(m2, s2, om, os);
    }
    __syncthreads();                 // reuse shm/shs
    if (lane == 0) { shm[warp] = m2; shs[warp] = s2; }
    __syncthreads();
    __shared__ float sz;
    if (tid == 0) {
        float mm = shm[0], sacc = shs[0];
        #pragma unroll
        for (int k = 1; k < 8; k++) lse_merge(mm, sacc, shm[k], shs[k]);
        sz = mm + logf(sacc);
    }
    __syncthreads();
    float logz = sz;
    if (v < V) d_out[v] = g_logits[v] - logz;
}

// ---------------- launch ---------------------------------------------------
extern "C" void kernel_launch(void* const* d_in, const int* in_sizes, int n_in,
                              void* d_out, int out_size) {
    const int*   word     = (const int*)  d_in[0];
    const float* last_ctx = (const float*)d_in[1];
    const float* last_h   = (const float*)d_in[2];
    const float* enc      = (const float*)d_in[3];
    const float* emb      = (const float*)d_in[4];
    const float* w_ih     = (const float*)d_in[5];
    const float* w_hh     = (const float*)d_in[6];
    const float* b_ih     = (const float*)d_in[7];
    const float* b_hh     = (const float*)d_in[8];
    const float* out_w    = (const float*)d_in[9];
    const float* out_b    = (const float*)d_in[10];
    float* out = (float*)d_out;

    gru_attn_kernel<<<ABLK, 256>>>(word, last_ctx, last_h, enc, emb,
                                   w_ih, w_hh, b_ih, b_hh, out);
    logits_kernel<<<V, 128>>>(out_w, out_b);
    lse_write_kernel<<<LBLK, 256>>>(out);
}

// round 11
// speedup vs baseline: 1.2432x; 1.0259x over previous
#include <cuda_runtime.h>
#include <math.h>
#include <float.h>

#define H 1024
#define V 50257
#define S 4096
#define ABLK 256      // kernel A blocks (persistent, co-resident)
#define LBLK 197      // kernel C blocks

// ---------------- scratch (device globals; no allocation allowed) ----------
__device__ float g_hnew[H];
__device__ float g_context[H];
__device__ float g_bmax[ABLK];
__device__ float g_bsum[ABLK];
__device__ float g_ctx_part[ABLK * H];
__device__ float g_logits[V];
__device__ float g_lse_m[LBLK];
__device__ float g_lse_s[LBLK];
__device__ unsigned int g_cnt;          // returns to 0 after every barrier
__device__ unsigned int g_gen;          // monotonic; wrap-safe

// ---------------- helpers --------------------------------------------------
__device__ __forceinline__ float dot4(float4 a, float4 b) {
    return a.x * b.x + a.y * b.y + a.z * b.z + a.w * b.w;
}
__device__ __forceinline__ float warp_sum(float v) {
    #pragma unroll
    for (int o = 16; o > 0; o >>= 1) v += __shfl_xor_sync(0xffffffffu, v, o);
    return v;
}
__device__ __forceinline__ float warp_max(float v) {
    #pragma unroll
    for (int o = 16; o > 0; o >>= 1) v = fmaxf(v, __shfl_xor_sync(0xffffffffu, v, o));
    return v;
}
__device__ __forceinline__ void lse_merge(float& m, float& s, float om, float os) {
    float nm = fmaxf(m, om);              // operands finite (-FLT_MAX pad)
    s = s * expf(m - nm) + os * expf(om - nm);
    m = nm;
}
// generation-based grid barrier; stateless after release (cnt back to 0).
__device__ __forceinline__ void gbar(unsigned int target) {
    __syncthreads();
    if (threadIdx.x == 0) {
        __threadfence();
        unsigned int gen = atomicAdd(&g_gen, 0u);   // read BEFORE arriving
        unsigned int old = atomicAdd(&g_cnt, 1u);
        if (old == target - 1) {
            atomicExch(&g_cnt, 0u);
            __threadfence();
            atomicAdd(&g_gen, 1u);                   // release
        } else {
            while (atomicAdd(&g_gen, 0u) == gen) __nanosleep(40);
        }
    }
    __syncthreads();
    __threadfence();
}

// ============ Kernel A: GRU + attention. 256 blocks x 256 threads ==========
// GRU: block b handles rows 4b..4b+3 CONCURRENTLY, 64 threads per row.
__global__ void __launch_bounds__(256, 2)
gru_attn_kernel(const int* __restrict__ word,
                const float* __restrict__ last_ctx,
                const float* __restrict__ last_h,
                const float* __restrict__ enc,
                const float* __restrict__ emb,
                const float* __restrict__ w_ih,
                const float* __restrict__ w_hh,
                const float* __restrict__ b_ih,
                const float* __restrict__ b_hh,
                float* __restrict__ d_out) {
    const int b = blockIdx.x;
    const int tid = threadIdx.x;
    const int warp = tid >> 5, lane = tid & 31;

    __shared__ float sc[16], ev[16], av[16];
    __shared__ float r8[8];
    __shared__ float4 r84[8];
    __shared__ float bc, bc2;

    // -------- Phase A: GRU, 4 rows in parallel --------
    {
        const int r = tid >> 6;               // row slot 0..3
        const int t = tid & 63;               // thread within row
        const int j = b * 4 + r;              // global hidden unit

        const float4* e4 = (const float4*)(emb + (size_t)word[0] * H);
        const float4* c4 = (const float4*)last_ctx;
        const float4* h4 = (const float4*)last_h;
        const float4* wr = (const float4*)(w_ih + (size_t)(j)       * 2 * H);
        const float4* wz = (const float4*)(w_ih + (size_t)(j + H)   * 2 * H);
        const float4* wn = (const float4*)(w_ih + (size_t)(j + 2*H) * 2 * H);
        const float4* ur = (const float4*)(w_hh + (size_t)(j)       * H);
        const float4* uz = (const float4*)(w_hh + (size_t)(j + H)   * H);
        const float4* un = (const float4*)(w_hh + (size_t)(j + 2*H) * H);

        float ar = 0.f, az = 0.f, an = 0.f, br2 = 0.f, bz = 0.f, bn = 0.f;
        #pragma unroll
        for (int k = 0; k < 8; k++) {
            int c = t + 64 * k;               // 0..511
            float4 x = (c < 256) ? e4[c] : c4[c - 256];
            ar += dot4(wr[c], x);
            az += dot4(wz[c], x);
            an += dot4(wn[c], x);
        }
        #pragma unroll
        for (int k = 0; k < 4; k++) {
            int c = t + 64 * k;               // 0..255
            float4 hh = h4[c];
            br2 += dot4(ur[c], hh);
            bz  += dot4(uz[c], hh);
            bn  += dot4(un[c], hh);
        }
        ar = warp_sum(ar); az = warp_sum(az); an = warp_sum(an);
        br2 = warp_sum(br2); bz = warp_sum(bz); bn = warp_sum(bn);

        __shared__ float red[6][8];           // [gate][warp]
        if (lane == 0) {
            red[0][warp] = ar;  red[1][warp] = az;  red[2][warp] = an;
            red[3][warp] = br2; red[4][warp] = bz;  red[5][warp] = bn;
        }
        __syncthreads();
        if (t == 0) {                         // 4 finisher threads, one per row
            int w0 = r * 2, w1 = r * 2 + 1;
            float ir = red[0][w0] + red[0][w1] + b_ih[j];
            float iz = red[1][w0] + red[1][w1] + b_ih[j + H];
            float in_ = red[2][w0] + red[2][w1] + b_ih[j + 2 * H];
            float hr = red[3][w0] + red[3][w1] + b_hh[j];
            float hz = red[4][w0] + red[4][w1] + b_hh[j + H];
            float hn = red[5][w0] + red[5][w1] + b_hh[j + 2 * H];
            float rg = 1.f / (1.f + expf(-(ir + hr)));
            float zg = 1.f / (1.f + expf(-(iz + hz)));
            float ng = tanhf(in_ + rg * hn);
            float hv = last_h[j];
            float hnew = (1.f - zg) * ng + zg * hv;
            g_hnew[j] = hnew;
            d_out[V + H + j] = hnew;          // h_new slot
        }
    }
    gbar(ABLK);

    // -------- Phase B: scores for rows [16b, 16b+16) --------
    const float4* enc4 = (const float4*)enc;
    #pragma unroll
    for (int rr = 0; rr < 2; rr++) {
        int local = warp * 2 + rr;
        const float4* e4 = enc4 + (size_t)(b * 16 + local) * 256;
        float a0 = 0.f, a1 = 0.f;
        #pragma unroll
        for (int k = 0; k < 8; k += 2) {
            a0 += dot4(e4[lane + 32 * k],       __ldcg(&((const float4*)g_hnew)[lane + 32 * k]));
            a1 += dot4(e4[lane + 32 * (k + 1)], __ldcg(&((const float4*)g_hnew)[lane + 32 * (k + 1)]));
        }
        float acc = warp_sum(a0 + a1);
        if (lane == 0) sc[local] = acc;
    }
    __syncthreads();
    if (tid < 32) {
        float v = (lane < 16) ? sc[lane] : -FLT_MAX;
        v = warp_max(v);
        if (lane == 0) g_bmax[b] = v;
    }
    gbar(ABLK);

    // -------- Phase C: global max, exp, block partial sum --------
    {
        float v = __ldcg(&g_bmax[tid]);
        v = warp_max(v);
        if (lane == 0) r8[warp] = v;
        __syncthreads();
        if (tid == 0) {
            float m = r8[0];
            #pragma unroll
            for (int k = 1; k < 8; k++) m = fmaxf(m, r8[k]);
            bc = m;
        }
        __syncthreads();
        float M = bc;
        if (tid < 16) ev[tid] = expf(sc[tid] - M);
        __syncthreads();
        if (tid < 32) {
            float e = (lane < 16) ? ev[lane] : 0.f;
            e = warp_sum(e);
            if (lane == 0) g_bsum[b] = e;
        }
    }
    gbar(ABLK);

    // -------- Phase D: normalize, attn out, ctx partial --------
    {
        float v = __ldcg(&g_bsum[tid]);
        v = warp_sum(v);
        if (lane == 0) r8[warp] = v;
        __syncthreads();
        if (tid == 0) {
            float z = r8[0];
            #pragma unroll
            for (int k = 1; k < 8; k++) z += r8[k];
            bc2 = 1.f / z;
        }
        __syncthreads();
        float invZ = bc2;
        if (tid < 16) {
            float a = ev[tid] * invZ;
            av[tid] = a;
            d_out[V + 2 * H + b * 16 + tid] = a;   // attn slot
        }
        __syncthreads();
        const float4* e4 = enc4 + (size_t)(b * 16) * 256;
        float4 acc = make_float4(0.f, 0.f, 0.f, 0.f);
        #pragma unroll
        for (int i = 0; i < 16; i++) {
            float a = av[i];
            float4 e = e4[(size_t)i * 256 + tid];  // L1-hot from phase B
            acc.x += a * e.x; acc.y += a * e.y; acc.z += a * e.z; acc.w += a * e.w;
        }
        ((float4*)g_ctx_part)[b * 256 + tid] = acc;
    }
    gbar(ABLK);

    // -------- Phase E: ctx reduce -> context[4b .. 4b+3] --------
    {
        float4 val = __ldcg(&((const float4*)g_ctx_part)[(size_t)tid * 256 + b]);
        val.x = warp_sum(val.x); val.y = warp_sum(val.y);
        val.z = warp_sum(val.z); val.w = warp_sum(val.w);
        if (lane == 0) r84[warp] = val;
        __syncthreads();
        if (tid == 0) {
            float4 s = r84[0];
            #pragma unroll
            for (int k = 1; k < 8; k++) {
                s.x += r84[k].x; s.y += r84[k].y; s.z += r84[k].z; s.w += r84[k].w;
            }
            ((float4*)g_context)[b] = s;
            d_out[V + 4 * b + 0] = s.x;            // context slot
            d_out[V + 4 * b + 1] = s.y;
            d_out[V + 4 * b + 2] = s.z;
            d_out[V + 4 * b + 3] = s.w;
        }
    }
}

// ============ Kernel B: logits. V blocks x 128 (proven ~6.9 TB/s) ==========
__global__ void __launch_bounds__(128) logits_kernel(const float* __restrict__ out_w,
                                                     const float* __restrict__ out_b) {
    const int v = blockIdx.x;
    const int tid = threadIdx.x;
    const float4* w4 = (const float4*)(out_w + (size_t)v * 2 * H);
    const float4* h4 = (const float4*)g_hnew;
    const float4* c4 = (const float4*)g_context;
    float acc = 0.f;
    #pragma unroll
    for (int k = 0; k < 4; k++) {
        int c = tid + 128 * k;
        float4 x = (k < 2) ? h4[c] : c4[c - 256];
        acc += dot4(w4[c], x);
    }
    acc = warp_sum(acc);
    __shared__ float red[4];
    if ((tid & 31) == 0) red[tid >> 5] = acc;
    __syncthreads();
    if (tid == 0) g_logits[v] = red[0] + red[1] + red[2] + red[3] + out_b[v];
}

// ============ Kernel C: fused logsumexp + write. 197 blocks x 256 ==========
__global__ void __launch_bounds__(256) lse_write_kernel(float* __restrict__ d_out) {
    const int b = blockIdx.x;
    const int tid = threadIdx.x;
    const int warp = tid >> 5, lane = tid & 31;
    const int v = b * 256 + tid;

    float m = (v < V) ? g_logits[v] : -FLT_MAX;
    float s = (v < V) ? 1.f : 0.f;
    #pragma unroll
    for (int o = 16; o > 0; o >>= 1) {
        float om = __shfl_xor_sync(0xffffffffu, m, o);
        float os = __shfl_xor_sync(0xffffffffu, s, o);
        lse_merge(m, s, om, os);
    }
    __shared__ float shm[8], shs[8];
    if (lane == 0) { shm[warp] = m; shs[warp] = s; }
    __syncthreads();
    if (tid == 0) {
        float mm = shm[0], sacc = shs[0];
        #pragma unroll
        for (int k = 1; k < 8; k++) lse_merge(mm, sacc, shm[k], shs[k]);
        g_lse_m[b] = mm;
        g_lse_s[b] = sacc;
    }
    gbar(LBLK);

    float m2 = (tid < LBLK) ? __ldcg(&g_lse_m[tid]) : -FLT_MAX;
    float s2 = (tid < LBLK) ? __ldcg(&g_lse_s[tid]) : 0.f;
    #pragma unroll
    for (int o = 16; o > 0; o >>= 1) {
        float om = __shfl_xor_sync(0xffffffffu, m2, o);
        float os = __shfl_xor_sync(0xffffffffu, s2, o);
        lse_merge(m2, s2, om, os);
    }
    __syncthreads();                 // reuse shm/shs
    if (lane == 0) { shm[warp] = m2; shs[warp] = s2; }
    __syncthreads();
    __shared__ float sz;
    if (tid == 0) {
        float mm = shm[0], sacc = shs[0];
        #pragma unroll
        for (int k = 1; k < 8; k++) lse_merge(mm, sacc, shm[k], shs[k]);
        sz = mm + logf(sacc);
    }
    __syncthreads();
    float logz = sz;
    if (v < V) d_out[v] = g_logits[v] - logz;
}

// ---------------- launch ---------------------------------------------------
extern "C" void kernel_launch(void* const* d_in, const int* in_sizes, int n_in,
                              void* d_out, int out_size) {
    const int*   word     = (const int*)  d_in[0];
    const float* last_ctx = (const float*)d_in[1];
    const float* last_h   = (const float*)d_in[2];
    const float* enc      = (const float*)d_in[3];
    const float* emb      = (const float*)d_in[4];
    const float* w_ih     = (const float*)d_in[5];
    const float* w_hh     = (const float*)d_in[6];
    const float* b_ih     = (const float*)d_in[7];
    const float* b_hh     = (const float*)d_in[8];
    const float* out_w    = (const float*)d_in[9];
    const float* out_b    = (const float*)d_in[10];
    float* out = (float*)d_out;

    gru_attn_kernel<<<ABLK, 256>>>(word, last_ctx, last_h, enc, emb,
                                   w_ih, w_hh, b_ih, b_hh, out);
    logits_kernel<<<V, 128>>>(out_w, out_b);
    lse_write_kernel<<<LBLK, 256>>>(out);
}